// round 1
// baseline (speedup 1.0000x reference)
#include <cuda_runtime.h>
#include <cstdint>

// Problem constants
constexpr int B_   = 16;
constexpr int CIN  = 128;
constexpr int H_   = 64;
constexpr int W_   = 64;
constexpr int COUT = 256;
constexpr int HW   = H_ * W_;          // 4096
constexpr int KD   = CIN * 9;          // 1152  (GEMM K)
constexpr int NPIX = B_ * HW;          // 65536 (GEMM N)

// Scratch (device globals: allocation-free per harness rules)
__device__ float g_off[B_ * 18 * HW];                 // offset conv output, (B,18,H,W)
__device__ float g_S[(size_t)KD * NPIX];              // sampled matrix [c*9+k][b*4096+hw], 302 MB

// ---------------------------------------------------------------------------
// Kernel 1: offset conv — 3x3 same conv, Cin=128 -> 18 channels, + bias
// One thread per output pixel, all 18 channels accumulated in registers.
// Weights (18*1152 floats = 83 KB) staged in dynamic shared memory.
// ---------------------------------------------------------------------------
__global__ void off_conv_kernel(const float* __restrict__ x,
                                const float* __restrict__ w_off,
                                const float* __restrict__ b_off)
{
    extern __shared__ float sw[];  // 18 * KD floats
    const int tid = threadIdx.x;
    for (int i = tid; i < 18 * KD; i += blockDim.x) sw[i] = w_off[i];
    __syncthreads();

    const int p  = blockIdx.x * blockDim.x + tid;   // 0..65535
    const int b  = p >> 12;
    const int hw = p & 4095;
    const int ho = hw >> 6;
    const int wo = hw & 63;

    float acc[18];
#pragma unroll
    for (int j = 0; j < 18; j++) acc[j] = b_off[j];

    const float* xb = x + (size_t)b * CIN * HW;
    for (int c = 0; c < CIN; c++) {
        const float* xc  = xb + c * HW;
        const float* swc = sw + c * 9;
#pragma unroll
        for (int ky = 0; ky < 3; ky++) {
            const int iy = ho - 1 + ky;
            if (iy < 0 || iy > 63) continue;
#pragma unroll
            for (int kx = 0; kx < 3; kx++) {
                const int ix = wo - 1 + kx;
                if (ix < 0 || ix > 63) continue;
                const float v = xc[iy * 64 + ix];
                const float* wp = swc + ky * 3 + kx;   // stride KD between channels j
#pragma unroll
                for (int j = 0; j < 18; j++) acc[j] += v * wp[j * KD];
            }
        }
    }

    float* ob = g_off + (size_t)b * 18 * HW + hw;
#pragma unroll
    for (int j = 0; j < 18; j++) ob[j * HW] = acc[j];
}

// ---------------------------------------------------------------------------
// Kernel 2: bilinear sampling -> S[(c*9+k)][b*4096 + hw]
// grid: (16 pixel-chunks, 9 kernel-taps, 16 batches), 256 threads.
// Each thread handles one (b,k,pixel) site: weights/corner indices computed
// once, then a 128-iteration c-loop (4 L2-resident gathers + 1 coalesced STG).
// ---------------------------------------------------------------------------
__global__ void sample_kernel(const float* __restrict__ x)
{
    const int b   = blockIdx.z;
    const int k   = blockIdx.y;              // 0..8
    const int pix = blockIdx.x * blockDim.x + threadIdx.x;  // 0..4095
    const int ho  = pix >> 6;
    const int wo  = pix & 63;

    const float* offb = g_off + ((size_t)b * 18 + 2 * k) * HW;
    const float oy = offb[pix];
    const float ox = offb[HW + pix];

    const float ys = (float)(ho - 1 + (k / 3)) + oy;
    const float xs = (float)(wo - 1 + (k % 3)) + ox;

    const float y0f = floorf(ys), x0f = floorf(xs);
    const float wy1 = ys - y0f,  wx1 = xs - x0f;
    const float wy0 = 1.0f - wy1, wx0 = 1.0f - wx1;

    const int y0 = (int)y0f, x0 = (int)x0f;
    const int y1 = y0 + 1,   x1 = x0 + 1;
    const bool vy0 = (y0 >= 0) && (y0 < H_);
    const bool vy1 = (y1 >= 0) && (y1 < H_);
    const bool vx0 = (x0 >= 0) && (x0 < W_);
    const bool vx1 = (x1 >= 0) && (x1 < W_);

    const int y0c = min(max(y0, 0), H_ - 1), y1c = min(max(y1, 0), H_ - 1);
    const int x0c = min(max(x0, 0), W_ - 1), x1c = min(max(x1, 0), W_ - 1);

    const float w00 = wy0 * wx0 * ((vy0 && vx0) ? 1.0f : 0.0f);
    const float w01 = wy0 * wx1 * ((vy0 && vx1) ? 1.0f : 0.0f);
    const float w10 = wy1 * wx0 * ((vy1 && vx0) ? 1.0f : 0.0f);
    const float w11 = wy1 * wx1 * ((vy1 && vx1) ? 1.0f : 0.0f);

    const int i00 = y0c * 64 + x0c, i01 = y0c * 64 + x1c;
    const int i10 = y1c * 64 + x0c, i11 = y1c * 64 + x1c;

    const float* xb = x + (size_t)b * CIN * HW;
    float* Sp = g_S + (size_t)k * NPIX + b * HW + pix;   // row k, column (b,pix)

#pragma unroll 4
    for (int c = 0; c < CIN; c++) {
        const float* xc = xb + c * HW;
        const float v = xc[i00] * w00 + xc[i01] * w01 +
                        xc[i10] * w10 + xc[i11] * w11;
        Sp[(size_t)(c * 9) * NPIX] = v;                  // row c*9+k
    }
}

// ---------------------------------------------------------------------------
// Kernel 3: GEMM  out[o][n] = sum_r W[o][r] * S[r][n]
//   M=256 (Cout), K=1152, N=65536.  128x128x8 tiles, 256 threads, 8x8/thread.
//   Epilogue scatters column n = b*4096+hw into NCHW output.
// ---------------------------------------------------------------------------
constexpr int BM = 128, BN = 128, BK = 8;

__global__ __launch_bounds__(256) void gemm_kernel(const float* __restrict__ Wd,
                                                   float* __restrict__ out)
{
    __shared__ float As[BK][BM];
    __shared__ float Bs[BK][BN];

    const int tid = threadIdx.x;
    const int tx  = tid & 15;        // 0..15 -> n micro-tile
    const int ty  = tid >> 4;        // 0..15 -> m micro-tile
    const int bn0 = blockIdx.x * BN;
    const int bm0 = blockIdx.y * BM;

    float acc[8][8] = {};

    const int arow = tid >> 1;             // 0..127
    const int acol = (tid & 1) * 4;        // 0 or 4
    const int brow = tid >> 5;             // 0..7
    const int bcol = (tid & 31) * 4;       // 0..124

    const float* Aptr = Wd + (size_t)(bm0 + arow) * KD + acol;
    const float* Bptr = g_S + (size_t)brow * NPIX + bn0 + bcol;

    for (int k0 = 0; k0 < KD; k0 += BK) {
        const float4 av = *(const float4*)(Aptr + k0);
        As[acol + 0][arow] = av.x;
        As[acol + 1][arow] = av.y;
        As[acol + 2][arow] = av.z;
        As[acol + 3][arow] = av.w;
        *(float4*)&Bs[brow][bcol] = *(const float4*)(Bptr + (size_t)k0 * NPIX);
        __syncthreads();

#pragma unroll
        for (int kk = 0; kk < BK; kk++) {
            float a[8], bb[8];
#pragma unroll
            for (int i = 0; i < 8; i++) a[i]  = As[kk][ty * 8 + i];
#pragma unroll
            for (int j = 0; j < 8; j++) bb[j] = Bs[kk][tx * 8 + j];
#pragma unroll
            for (int i = 0; i < 8; i++)
#pragma unroll
                for (int j = 0; j < 8; j++) acc[i][j] += a[i] * bb[j];
        }
        __syncthreads();
    }

    // bn0 spans a single batch (4096 % 128 == 0)
    const int  bidx   = bn0 >> 12;
    const int  hwbase = (bn0 & 4095) + tx * 8;
    float* ob = out + (size_t)bidx * COUT * HW;

#pragma unroll
    for (int i = 0; i < 8; i++) {
        const int o = bm0 + ty * 8 + i;
        float* op = ob + (size_t)o * HW + hwbase;
#pragma unroll
        for (int j = 0; j < 8; j += 4) {
            float4 v = make_float4(acc[i][j], acc[i][j + 1], acc[i][j + 2], acc[i][j + 3]);
            *(float4*)(op + j) = v;
        }
    }
}

// ---------------------------------------------------------------------------
extern "C" void kernel_launch(void* const* d_in, const int* in_sizes, int n_in,
                              void* d_out, int out_size)
{
    const float* x     = (const float*)d_in[0];
    const float* w_off = (const float*)d_in[1];
    const float* b_off = (const float*)d_in[2];
    const float* w_def = (const float*)d_in[3];
    float* out = (float*)d_out;

    const int smem_off = 18 * KD * sizeof(float);   // 82944 bytes
    cudaFuncSetAttribute(off_conv_kernel,
                         cudaFuncAttributeMaxDynamicSharedMemorySize, smem_off);

    off_conv_kernel<<<NPIX / 256, 256, smem_off>>>(x, w_off, b_off);
    sample_kernel<<<dim3(HW / 256, 9, B_), 256>>>(x);
    gemm_kernel<<<dim3(NPIX / BN, COUT / BM), 256>>>(w_def, out);
}

// round 4
// speedup vs baseline: 1.7259x; 1.7259x over previous
#include <cuda_runtime.h>
#include <cuda_bf16.h>
#include <cstdint>

// ---------------------------------------------------------------- constants
constexpr int B_   = 16;
constexpr int CIN  = 128;
constexpr int H_   = 64;
constexpr int W_   = 64;
constexpr int COUT = 256;
constexpr int HW   = H_ * W_;        // 4096
constexpr int KD   = CIN * 9;        // 1152
constexpr int NPIX = B_ * HW;        // 65536

constexpr int KB16 = KD / 16;        // 72 k16-blocks per plane
constexpr int NIT  = 108;            // pipeline iterations (k32 each, 3 terms)
constexpr int NPB  = NPIX / 8;       // 8192 pixel-octets

// ---------------------------------------------------------------- scratch
// A fragments: [kb][mb(16)][lane(32)][reg(4)] u32   (1.18 MB per plane)
// B fragments: [kb][pb(8192)][lane(32)][reg(2)] u32 (151 MB per plane)
__device__ __align__(1024) float    g_off[B_ * 18 * HW];
__device__ __align__(1024) uint32_t g_Ahi[KB16 * 16 * 32 * 4];
__device__ __align__(1024) uint32_t g_Alo[KB16 * 16 * 32 * 4];
__device__ __align__(1024) uint32_t g_Bhi[(size_t)KB16 * NPB * 32 * 2];
__device__ __align__(1024) uint32_t g_Blo[(size_t)KB16 * NPB * 32 * 2];

// ---------------------------------------------------------------- helpers
__device__ __forceinline__ uint32_t smem_u32(const void* p) {
    uint32_t a;
    asm("{ .reg .u64 t; cvta.to.shared.u64 t, %1; cvt.u32.u64 %0, t; }" : "=r"(a) : "l"(p));
    return a;
}
#define CPA16(sa, gp) asm volatile("cp.async.cg.shared.global [%0], [%1], 16;" :: "r"(sa), "l"(gp) : "memory")
#define CPA_COMMIT()  asm volatile("cp.async.commit_group;" ::: "memory")

#define LDS128(r0, r1, r2, r3, a) \
    asm volatile("ld.shared.v4.b32 {%0,%1,%2,%3}, [%4];" : "=r"(r0), "=r"(r1), "=r"(r2), "=r"(r3) : "r"(a))
#define LDS64(r0, r1, a) \
    asm volatile("ld.shared.v2.b32 {%0,%1}, [%2];" : "=r"(r0), "=r"(r1) : "r"(a))

#define MMA16816(c, a, b)                                                     \
    asm volatile("mma.sync.aligned.m16n8k16.row.col.f32.bf16.bf16.f32 "       \
        "{%0,%1,%2,%3}, {%4,%5,%6,%7}, {%8,%9}, {%0,%1,%2,%3};"               \
        : "+f"((c)[0]), "+f"((c)[1]), "+f"((c)[2]), "+f"((c)[3])              \
        : "r"((a)[0]), "r"((a)[1]), "r"((a)[2]), "r"((a)[3]),                 \
          "r"((b)[0]), "r"((b)[1]))

__device__ __forceinline__ uint32_t pack_bf2(__nv_bfloat16 lo_k, __nv_bfloat16 hi_k) {
    __nv_bfloat162 t;
    t.x = lo_k;   // lower k in low 16 bits
    t.y = hi_k;
    return *(uint32_t*)&t;
}

// ---------------------------------------------------------------------------
// Kernel 0: weight prep — bf16 hi/lo split, fragment-ready layout, K=tap*128+c
// ---------------------------------------------------------------------------
__global__ void wprep_kernel(const float* __restrict__ w_def)
{
    const int idx = blockIdx.x * blockDim.x + threadIdx.x;   // over COUT*KD
    if (idx >= COUT * KD) return;
    const int o   = idx / KD;
    const int r   = idx % KD;          // c*9 + tap (w_def ordering)
    const int c   = r / 9;
    const int tap = r % 9;

    const float w = w_def[idx];
    const __nv_bfloat16 hi = __float2bfloat16_rn(w);
    const __nv_bfloat16 lo = __float2bfloat16_rn(w - __bfloat162float(hi));

    const int knew = tap * 128 + c;
    const int kb = knew >> 4, kk = knew & 15;
    const int mb = o >> 4,    mr = o & 15;
    const int lane = (mr & 7) * 4 + ((kk & 7) >> 1);
    const int reg  = (mr >> 3) + ((kk >> 3) << 1);
    const size_t u16i = ((((size_t)kb * 16 + mb) * 32 + lane) * 4 + reg) * 2 + (kk & 1);

    ((unsigned short*)g_Ahi)[u16i] = *(const unsigned short*)&hi;
    ((unsigned short*)g_Alo)[u16i] = *(const unsigned short*)&lo;
}

// ---------------------------------------------------------------------------
// Kernel 1: offset conv (2 pixels/thread, weights in SMEM)
// ---------------------------------------------------------------------------
__global__ void off_conv_kernel(const float* __restrict__ x,
                                const float* __restrict__ w_off,
                                const float* __restrict__ b_off)
{
    extern __shared__ float sw[];     // 18*1152
    const int tid = threadIdx.x;
    for (int i = tid; i < 18 * KD; i += blockDim.x) sw[i] = w_off[i];
    __syncthreads();

    const int p   = blockIdx.x * blockDim.x + tid;   // 0..32767
    const int b   = p >> 11;
    const int rem = p & 2047;
    const int ho  = rem >> 5;
    const int wo  = (rem & 31) * 2;

    float acc[18][2];
#pragma unroll
    for (int j = 0; j < 18; j++) { acc[j][0] = b_off[j]; acc[j][1] = acc[j][0]; }

    const float* xb = x + (size_t)b * CIN * HW;
    for (int c = 0; c < CIN; c++) {
        const float* xc = xb + c * HW;
        float r[3][4];
#pragma unroll
        for (int dy = 0; dy < 3; dy++) {
            const int iy = ho - 1 + dy;
            const bool vy = (iy >= 0) && (iy < 64);
#pragma unroll
            for (int dx = 0; dx < 4; dx++) {
                const int ix = wo - 1 + dx;
                r[dy][dx] = (vy && ix >= 0 && ix < 64) ? xc[iy * 64 + ix] : 0.0f;
            }
        }
        const float* swc = sw + c * 9;
#pragma unroll
        for (int ky = 0; ky < 3; ky++)
#pragma unroll
            for (int kx = 0; kx < 3; kx++) {
                const float v0 = r[ky][kx];
                const float v1 = r[ky][kx + 1];
                const float* wp = swc + ky * 3 + kx;
#pragma unroll
                for (int j = 0; j < 18; j++) {
                    const float wv = wp[j * KD];
                    acc[j][0] += wv * v0;
                    acc[j][1] += wv * v1;
                }
            }
    }

    float* ob = g_off + (size_t)b * 18 * HW + ho * 64 + wo;
#pragma unroll
    for (int j = 0; j < 18; j++) { ob[j * HW] = acc[j][0]; ob[j * HW + 1] = acc[j][1]; }
}

// ---------------------------------------------------------------------------
// Kernel 2: bilinear sampling -> mma-fragment-ready bf16 hi/lo planes
// K ordering k = tap*128 + c makes channel pairs (c, c+1) pack into one u32.
// ---------------------------------------------------------------------------
__global__ void sample_kernel(const float* __restrict__ x)
{
    const int b   = blockIdx.z;
    const int tap = blockIdx.y;                              // 0..8
    const int pix = blockIdx.x * blockDim.x + threadIdx.x;   // 0..4095
    const int ho  = pix >> 6;
    const int wo  = pix & 63;

    const float* offb = g_off + ((size_t)b * 18 + 2 * tap) * HW;
    const float oy = offb[pix];
    const float ox = offb[HW + pix];

    const float ys = (float)(ho - 1 + (tap / 3)) + oy;
    const float xs = (float)(wo - 1 + (tap % 3)) + ox;

    const float y0f = floorf(ys), x0f = floorf(xs);
    const float wy1 = ys - y0f,  wx1 = xs - x0f;
    const float wy0 = 1.0f - wy1, wx0 = 1.0f - wx1;

    const int y0 = (int)y0f, x0 = (int)x0f;
    const int y1 = y0 + 1,   x1 = x0 + 1;
    const bool vy0 = (y0 >= 0) && (y0 < H_);
    const bool vy1 = (y1 >= 0) && (y1 < H_);
    const bool vx0 = (x0 >= 0) && (x0 < W_);
    const bool vx1 = (x1 >= 0) && (x1 < W_);

    const int y0c = min(max(y0, 0), H_ - 1), y1c = min(max(y1, 0), H_ - 1);
    const int x0c = min(max(x0, 0), W_ - 1), x1c = min(max(x1, 0), W_ - 1);

    const float w00 = wy0 * wx0 * ((vy0 && vx0) ? 1.0f : 0.0f);
    const float w01 = wy0 * wx1 * ((vy0 && vx1) ? 1.0f : 0.0f);
    const float w10 = wy1 * wx0 * ((vy1 && vx0) ? 1.0f : 0.0f);
    const float w11 = wy1 * wx1 * ((vy1 && vx1) ? 1.0f : 0.0f);

    const int i00 = y0c * 64 + x0c, i01 = y0c * 64 + x1c;
    const int i10 = y1c * 64 + x0c, i11 = y1c * 64 + x1c;

    const float* xb = x + (size_t)b * CIN * HW;

    const int gpix  = b * HW + pix;
    const int pb    = gpix >> 3;
    const int lanen = (gpix & 7) * 4;

#pragma unroll 2
    for (int c = 0; c < CIN; c += 2) {
        const float* xc0 = xb + c * HW;
        const float* xc1 = xc0 + HW;
        const float v0 = xc0[i00] * w00 + xc0[i01] * w01 + xc0[i10] * w10 + xc0[i11] * w11;
        const float v1 = xc1[i00] * w00 + xc1[i01] * w01 + xc1[i10] * w10 + xc1[i11] * w11;

        const __nv_bfloat16 h0 = __float2bfloat16_rn(v0);
        const __nv_bfloat16 h1 = __float2bfloat16_rn(v1);
        const __nv_bfloat16 l0 = __float2bfloat16_rn(v0 - __bfloat162float(h0));
        const __nv_bfloat16 l1 = __float2bfloat16_rn(v1 - __bfloat162float(h1));

        const int knew = tap * 128 + c;
        const int kb = knew >> 4, kk = knew & 15;
        const int lane = lanen + ((kk & 7) >> 1);
        const int reg  = kk >> 3;
        const size_t idx = (((size_t)kb * NPB + pb) * 32 + lane) * 2 + reg;
        g_Bhi[idx] = pack_bf2(h0, h1);
        g_Blo[idx] = pack_bf2(l0, l1);
    }
}

// ---------------------------------------------------------------------------
// Kernel 3: bf16 HMMA GEMM, 3-term hi/lo.  CTA = m128 x n128, 8 warps.
// 4-stage cp.async pipeline, k32 per stage.
// ---------------------------------------------------------------------------
constexpr int STAGES = 4;
// per stage: A 2*8*32*4 u32 = 8KB, B 2*16*32*2 u32 = 8KB

__global__ __launch_bounds__(256) void gemm_kernel(float* __restrict__ out)
{
    extern __shared__ uint32_t smem[];
    uint32_t* Asm = smem;                    // STAGES * 2048 u32
    uint32_t* Bsm = smem + STAGES * 2048;    // STAGES * 2048 u32

    const int tid  = threadIdx.x;
    const int wid  = tid >> 5;
    const int lane = tid & 31;
    const int mhalf = blockIdx.x;            // 0,1  (inner -> L2 reuse of B)
    const int ntile = blockIdx.y;            // 0..511
    const int mb0 = mhalf * 8;
    const int pb0 = ntile * 16;

    const uint32_t a_smem0 = smem_u32(Asm);
    const uint32_t b_smem0 = smem_u32(Bsm);

    auto load_stage = [&](int st, int slot) {
        const int t  = st / 36;                       // term 0,1,2
        const int kb = (st % 36) * 2;                 // plane-local k16 index
        const uint32_t* Ap = (t == 1) ? g_Alo : g_Ahi;
        const uint32_t* Bp = (t == 2) ? g_Blo : g_Bhi;
        const uint32_t a_s = a_smem0 + slot * 8192;
        const uint32_t b_s = b_smem0 + slot * 8192;
#pragma unroll
        for (int q = 0; q < 2; q++) {
            const uint32_t* asrc = Ap + ((size_t)(kb + q) * 16 + mb0) * 128;
            const uint32_t* bsrc = Bp + ((size_t)(kb + q) * NPB + pb0) * 64;
            CPA16(a_s + q * 4096 + tid * 16, asrc + tid * 4);
            CPA16(b_s + q * 4096 + tid * 16, bsrc + tid * 4);
        }
        CPA_COMMIT();
    };

    float acc[4][4][4] = {};

    for (int s = 0; s < STAGES - 1; s++) load_stage(s, s);

    const int wm = wid >> 2;     // 0,1 -> m64
    const int wn = wid & 3;      // 0..3 -> n32

    for (int st = 0; st < NIT; st++) {
        if (st + STAGES - 1 < NIT) load_stage(st + STAGES - 1, (st + STAGES - 1) % STAGES);
        else                       CPA_COMMIT();
        asm volatile("cp.async.wait_group %0;" :: "n"(STAGES - 2));
        __syncthreads();

        const int slot = st % STAGES;
        const uint32_t a_s = a_smem0 + slot * 8192;
        const uint32_t b_s = b_smem0 + slot * 8192;

#pragma unroll
        for (int q = 0; q < 2; q++) {
            uint32_t a[4][4], b[4][2];
#pragma unroll
            for (int i = 0; i < 4; i++)
                LDS128(a[i][0], a[i][1], a[i][2], a[i][3],
                       a_s + q * 4096 + ((wm * 4 + i) * 32 + lane) * 16);
#pragma unroll
            for (int j = 0; j < 4; j++)
                LDS64(b[j][0], b[j][1],
                      b_s + q * 4096 + ((wn * 4 + j) * 32 + lane) * 8);
#pragma unroll
            for (int i = 0; i < 4; i++)
#pragma unroll
                for (int j = 0; j < 4; j++)
                    MMA16816(acc[i][j], a[i], b[j]);
        }
        __syncthreads();
    }

    // epilogue
    const int cout_base = mhalf * 128 + wm * 64;
    const int n_base    = ntile * 128 + wn * 32;
    const int bidx = n_base >> 12;
    const int hwb  = n_base & 4095;

#pragma unroll
    for (int i = 0; i < 4; i++) {
        const int m0 = cout_base + i * 16 + (lane >> 2);
        float* row1 = out + ((size_t)(bidx * COUT + m0)) * HW + hwb;
        float* row2 = row1 + (size_t)8 * HW;
#pragma unroll
        for (int j = 0; j < 4; j++) {
            const int n0 = j * 8 + (lane & 3) * 2;
            *(float2*)(row1 + n0) = make_float2(acc[i][j][0], acc[i][j][1]);
            *(float2*)(row2 + n0) = make_float2(acc[i][j][2], acc[i][j][3]);
        }
    }
}

// ---------------------------------------------------------------------------
extern "C" void kernel_launch(void* const* d_in, const int* in_sizes, int n_in,
                              void* d_out, int out_size)
{
    const float* x     = (const float*)d_in[0];
    const float* w_off = (const float*)d_in[1];
    const float* b_off = (const float*)d_in[2];
    const float* w_def = (const float*)d_in[3];
    float* out = (float*)d_out;

    const int smem_off = 18 * KD * sizeof(float);        // 82944
    cudaFuncSetAttribute(off_conv_kernel,
                         cudaFuncAttributeMaxDynamicSharedMemorySize, smem_off);
    const int smem_gemm = STAGES * 16384;                // 65536
    cudaFuncSetAttribute(gemm_kernel,
                         cudaFuncAttributeMaxDynamicSharedMemorySize, smem_gemm);

    wprep_kernel<<<(COUT * KD + 255) / 256, 256>>>(w_def);
    off_conv_kernel<<<(NPIX / 2) / 128, 128, smem_off>>>(x, w_off, b_off);
    sample_kernel<<<dim3(HW / 256, 9, B_), 256>>>(x);
    gemm_kernel<<<dim3(2, NPIX / 128), 256, smem_gemm>>>(out);
}

// round 6
// speedup vs baseline: 2.2662x; 1.3131x over previous
#include <cuda_runtime.h>
#include <cuda_bf16.h>
#include <cstdint>

// ---------------------------------------------------------------- constants
constexpr int B_   = 16;
constexpr int CIN  = 128;
constexpr int H_   = 64;
constexpr int W_   = 64;
constexpr int COUT = 256;
constexpr int HW   = H_ * W_;        // 4096
constexpr int KD   = CIN * 9;        // 1152
constexpr int NPIX = B_ * HW;        // 65536

constexpr int KB16 = KD / 16;        // 72 k16-blocks per plane
constexpr int NIT  = 108;            // pipeline iterations (k32 each, 3 terms)
constexpr int NPB  = NPIX / 8;       // 8192 pixel-octets

// ---------------------------------------------------------------- scratch
__device__ __align__(1024) float    g_off[B_ * 18 * HW];
__device__ __align__(1024) uint32_t g_Ahi[KB16 * 16 * 32 * 4];
__device__ __align__(1024) uint32_t g_Alo[KB16 * 16 * 32 * 4];
__device__ __align__(1024) uint32_t g_Bhi[(size_t)KB16 * NPB * 32 * 2];
__device__ __align__(1024) uint32_t g_Blo[(size_t)KB16 * NPB * 32 * 2];

// ---------------------------------------------------------------- helpers
__device__ __forceinline__ uint32_t smem_u32(const void* p) {
    uint32_t a;
    asm("{ .reg .u64 t; cvta.to.shared.u64 t, %1; cvt.u32.u64 %0, t; }" : "=r"(a) : "l"(p));
    return a;
}
#define CPA16(sa, gp) asm volatile("cp.async.cg.shared.global [%0], [%1], 16;" :: "r"(sa), "l"(gp) : "memory")
#define CPA_COMMIT()  asm volatile("cp.async.commit_group;" ::: "memory")

#define LDS128(r0, r1, r2, r3, a) \
    asm volatile("ld.shared.v4.b32 {%0,%1,%2,%3}, [%4];" : "=r"(r0), "=r"(r1), "=r"(r2), "=r"(r3) : "r"(a))
#define LDS64(r0, r1, a) \
    asm volatile("ld.shared.v2.b32 {%0,%1}, [%2];" : "=r"(r0), "=r"(r1) : "r"(a))

#define MMA16816(c, a, b)                                                     \
    asm volatile("mma.sync.aligned.m16n8k16.row.col.f32.bf16.bf16.f32 "       \
        "{%0,%1,%2,%3}, {%4,%5,%6,%7}, {%8,%9}, {%0,%1,%2,%3};"               \
        : "+f"((c)[0]), "+f"((c)[1]), "+f"((c)[2]), "+f"((c)[3])              \
        : "r"((a)[0]), "r"((a)[1]), "r"((a)[2]), "r"((a)[3]),                 \
          "r"((b)[0]), "r"((b)[1]))

__device__ __forceinline__ uint32_t pack_bf2(__nv_bfloat16 lo_k, __nv_bfloat16 hi_k) {
    __nv_bfloat162 t;
    t.x = lo_k;   // lower k in low 16 bits
    t.y = hi_k;
    return *(uint32_t*)&t;
}

// ---------------------------------------------------------------------------
// Kernel 0: weight prep — bf16 hi/lo split, fragment-ready layout, K=tap*128+c
// ---------------------------------------------------------------------------
__global__ void wprep_kernel(const float* __restrict__ w_def)
{
    const int idx = blockIdx.x * blockDim.x + threadIdx.x;   // over COUT*KD
    if (idx >= COUT * KD) return;
    const int o   = idx / KD;
    const int r   = idx % KD;          // c*9 + tap (w_def ordering)
    const int c   = r / 9;
    const int tap = r % 9;

    const float w = w_def[idx];
    const __nv_bfloat16 hi = __float2bfloat16_rn(w);
    const __nv_bfloat16 lo = __float2bfloat16_rn(w - __bfloat162float(hi));

    const int knew = tap * 128 + c;
    const int kb = knew >> 4, kk = knew & 15;
    const int mb = o >> 4,    mr = o & 15;
    const int lane = (mr & 7) * 4 + ((kk & 7) >> 1);
    const int reg  = (mr >> 3) + ((kk >> 3) << 1);
    const size_t u16i = ((((size_t)kb * 16 + mb) * 32 + lane) * 4 + reg) * 2 + (kk & 1);

    ((unsigned short*)g_Ahi)[u16i] = *(const unsigned short*)&hi;
    ((unsigned short*)g_Alo)[u16i] = *(const unsigned short*)&lo;
}

// ---------------------------------------------------------------------------
// Kernel 1: offset conv — 4 pixels/thread, weights broadcast from SMEM
// ---------------------------------------------------------------------------
__global__ __launch_bounds__(128) void off_conv_kernel(const float* __restrict__ x,
                                                       const float* __restrict__ w_off,
                                                       const float* __restrict__ b_off)
{
    extern __shared__ float sw[];     // 18*1152
    const int tid = threadIdx.x;
    for (int i = tid; i < 18 * KD; i += blockDim.x) sw[i] = w_off[i];
    __syncthreads();

    const int p   = blockIdx.x * blockDim.x + tid;   // 0..16383
    const int b   = p >> 10;
    const int rem = p & 1023;
    const int ho  = rem >> 4;
    const int wo  = (rem & 15) * 4;

    float acc[18][4];
#pragma unroll
    for (int j = 0; j < 18; j++) {
        const float bj = b_off[j];
#pragma unroll
        for (int q = 0; q < 4; q++) acc[j][q] = bj;
    }

    const float* xb = x + (size_t)b * CIN * HW;
    for (int c = 0; c < CIN; c++) {
        const float* xc = xb + c * HW;
        float r[3][6];
#pragma unroll
        for (int dy = 0; dy < 3; dy++) {
            const int iy = ho - 1 + dy;
            const bool vy = (iy >= 0) && (iy < 64);
#pragma unroll
            for (int dx = 0; dx < 6; dx++) {
                const int ix = wo - 1 + dx;
                r[dy][dx] = (vy && ix >= 0 && ix < 64) ? xc[iy * 64 + ix] : 0.0f;
            }
        }
        const float* swc = sw + c * 9;
#pragma unroll
        for (int ky = 0; ky < 3; ky++)
#pragma unroll
            for (int kx = 0; kx < 3; kx++) {
                const float* wp = swc + ky * 3 + kx;
#pragma unroll
                for (int j = 0; j < 18; j++) {
                    const float wv = wp[j * KD];
#pragma unroll
                    for (int q = 0; q < 4; q++)
                        acc[j][q] += wv * r[ky][kx + q];
                }
            }
    }

    float* ob = g_off + (size_t)b * 18 * HW + ho * 64 + wo;
#pragma unroll
    for (int j = 0; j < 18; j++)
        *(float4*)(ob + j * HW) = make_float4(acc[j][0], acc[j][1], acc[j][2], acc[j][3]);
}

// ---------------------------------------------------------------------------
// Kernel 2: bilinear sampling -> mma-fragment-ready bf16 hi/lo planes
// (c, c+1, c+8, c+9) per group -> one uint2 store per plane
// ---------------------------------------------------------------------------
__global__ void sample_kernel(const float* __restrict__ x)
{
    const int b   = blockIdx.z;
    const int tap = blockIdx.y;                              // 0..8
    const int pix = blockIdx.x * blockDim.x + threadIdx.x;   // 0..4095
    const int ho  = pix >> 6;
    const int wo  = pix & 63;

    const float* offb = g_off + ((size_t)b * 18 + 2 * tap) * HW;
    const float oy = offb[pix];
    const float ox = offb[HW + pix];

    const float ys = (float)(ho - 1 + (tap / 3)) + oy;
    const float xs = (float)(wo - 1 + (tap % 3)) + ox;

    const float y0f = floorf(ys), x0f = floorf(xs);
    const float wy1 = ys - y0f,  wx1 = xs - x0f;
    const float wy0 = 1.0f - wy1, wx0 = 1.0f - wx1;

    const int y0 = (int)y0f, x0 = (int)x0f;
    const int y1 = y0 + 1,   x1 = x0 + 1;
    const bool vy0 = (y0 >= 0) && (y0 < H_);
    const bool vy1 = (y1 >= 0) && (y1 < H_);
    const bool vx0 = (x0 >= 0) && (x0 < W_);
    const bool vx1 = (x1 >= 0) && (x1 < W_);

    const int y0c = min(max(y0, 0), H_ - 1), y1c = min(max(y1, 0), H_ - 1);
    const int x0c = min(max(x0, 0), W_ - 1), x1c = min(max(x1, 0), W_ - 1);

    const float w00 = wy0 * wx0 * ((vy0 && vx0) ? 1.0f : 0.0f);
    const float w01 = wy0 * wx1 * ((vy0 && vx1) ? 1.0f : 0.0f);
    const float w10 = wy1 * wx0 * ((vy1 && vx0) ? 1.0f : 0.0f);
    const float w11 = wy1 * wx1 * ((vy1 && vx1) ? 1.0f : 0.0f);

    const int i00 = y0c * 64 + x0c, i01 = y0c * 64 + x1c;
    const int i10 = y1c * 64 + x0c, i11 = y1c * 64 + x1c;

    const float* xb = x + (size_t)b * CIN * HW;

    const int gpix  = b * HW + pix;
    const int pb    = gpix >> 3;
    const int lanen = (gpix & 7) * 4;

#pragma unroll 2
    for (int cb = 0; cb < 8; cb++) {
        const int kb = tap * 8 + cb;
#pragma unroll
        for (int pr = 0; pr < 4; pr++) {
            const int c0 = cb * 16 + pr * 2;
            const float* xa = xb + c0 * HW;
            float v[4];
#pragma unroll
            for (int u = 0; u < 4; u++) {
                const float* xc = xa + ((u >> 1) * 8 + (u & 1)) * HW;  // c0, c0+1, c0+8, c0+9
                v[u] = xc[i00] * w00 + xc[i01] * w01 + xc[i10] * w10 + xc[i11] * w11;
            }
            __nv_bfloat16 h[4], l[4];
#pragma unroll
            for (int u = 0; u < 4; u++) {
                h[u] = __float2bfloat16_rn(v[u]);
                l[u] = __float2bfloat16_rn(v[u] - __bfloat162float(h[u]));
            }
            const int lane = lanen + pr;
            const size_t base = (((size_t)kb * NPB + pb) * 32 + lane) * 2;
            *(uint2*)&g_Bhi[base] = make_uint2(pack_bf2(h[0], h[1]), pack_bf2(h[2], h[3]));
            *(uint2*)&g_Blo[base] = make_uint2(pack_bf2(l[0], l[1]), pack_bf2(l[2], l[3]));
        }
    }
}

// ---------------------------------------------------------------------------
// Kernel 3: bf16 HMMA GEMM, 3-term hi/lo.  CTA = m128 x n128, 8 warps.
// 5-stage cp.async pipeline, k32/stage, one barrier per stage (after wait,
// before next iteration's loads — covers both cp.async visibility and WAR).
// ---------------------------------------------------------------------------
constexpr int STAGES = 5;
// per stage: A 8KB + B 8KB

__global__ __launch_bounds__(256) void gemm_kernel(float* __restrict__ out)
{
    extern __shared__ uint32_t smem[];
    uint32_t* Asm = smem;                    // STAGES * 2048 u32
    uint32_t* Bsm = smem + STAGES * 2048;    // STAGES * 2048 u32

    const int tid  = threadIdx.x;
    const int wid  = tid >> 5;
    const int lane = tid & 31;
    const int mhalf = blockIdx.x;            // 0,1  (inner -> L2 reuse of B)
    const int ntile = blockIdx.y;            // 0..511
    const int mb0 = mhalf * 8;
    const int pb0 = ntile * 16;

    const uint32_t a_smem0 = smem_u32(Asm);
    const uint32_t b_smem0 = smem_u32(Bsm);

    auto load_stage = [&](int st, int slot) {
        const int t  = st / 36;                       // term 0,1,2
        const int kb = (st % 36) * 2;                 // plane-local k16 index
        const uint32_t* Ap = (t == 1) ? g_Alo : g_Ahi;
        const uint32_t* Bp = (t == 2) ? g_Blo : g_Bhi;
        const uint32_t a_s = a_smem0 + slot * 8192;
        const uint32_t b_s = b_smem0 + slot * 8192;
#pragma unroll
        for (int q = 0; q < 2; q++) {
            const uint32_t* asrc = Ap + ((size_t)(kb + q) * 16 + mb0) * 128;
            const uint32_t* bsrc = Bp + ((size_t)(kb + q) * NPB + pb0) * 64;
            CPA16(a_s + q * 4096 + tid * 16, asrc + tid * 4);
            CPA16(b_s + q * 4096 + tid * 16, bsrc + tid * 4);
        }
        CPA_COMMIT();
    };

    float acc[4][4][4] = {};

    for (int s = 0; s < STAGES - 1; s++) load_stage(s, s);
    // make all threads' group-0 copies visible before the first compute
    asm volatile("cp.async.wait_group %0;" :: "n"(STAGES - 2));
    __syncthreads();

    const int wm = wid >> 2;     // 0,1 -> m64
    const int wn = wid & 3;      // 0..3 -> n32

    for (int st = 0; st < NIT; st++) {
        if (st + STAGES - 1 < NIT) load_stage(st + STAGES - 1, (st + STAGES - 1) % STAGES);
        else                       CPA_COMMIT();
        asm volatile("cp.async.wait_group %0;" :: "n"(STAGES - 2));

        const int slot = st % STAGES;
        const uint32_t a_s = a_smem0 + slot * 8192;
        const uint32_t b_s = b_smem0 + slot * 8192;

#pragma unroll
        for (int q = 0; q < 2; q++) {
            uint32_t a[4][4], b[4][2];
#pragma unroll
            for (int i = 0; i < 4; i++)
                LDS128(a[i][0], a[i][1], a[i][2], a[i][3],
                       a_s + q * 4096 + ((wm * 4 + i) * 32 + lane) * 16);
#pragma unroll
            for (int j = 0; j < 4; j++)
                LDS64(b[j][0], b[j][1],
                      b_s + q * 4096 + ((wn * 4 + j) * 32 + lane) * 8);
#pragma unroll
            for (int i = 0; i < 4; i++)
#pragma unroll
                for (int j = 0; j < 4; j++)
                    MMA16816(acc[i][j], a[i], b[j]);
        }
        // end-of-stage barrier: (a) WAR for next load into slot st%STAGES's
        // successor, (b) publishes every thread's completed groups <= st+1
        __syncthreads();
    }

    // epilogue
    const int cout_base = mhalf * 128 + wm * 64;
    const int n_base    = ntile * 128 + wn * 32;
    const int bidx = n_base >> 12;
    const int hwb  = n_base & 4095;

#pragma unroll
    for (int i = 0; i < 4; i++) {
        const int m0 = cout_base + i * 16 + (lane >> 2);
        float* row1 = out + ((size_t)(bidx * COUT + m0)) * HW + hwb;
        float* row2 = row1 + (size_t)8 * HW;
#pragma unroll
        for (int j = 0; j < 4; j++) {
            const int n0 = j * 8 + (lane & 3) * 2;
            *(float2*)(row1 + n0) = make_float2(acc[i][j][0], acc[i][j][1]);
            *(float2*)(row2 + n0) = make_float2(acc[i][j][2], acc[i][j][3]);
        }
    }
}

// ---------------------------------------------------------------------------
extern "C" void kernel_launch(void* const* d_in, const int* in_sizes, int n_in,
                              void* d_out, int out_size)
{
    const float* x     = (const float*)d_in[0];
    const float* w_off = (const float*)d_in[1];
    const float* b_off = (const float*)d_in[2];
    const float* w_def = (const float*)d_in[3];
    float* out = (float*)d_out;

    const int smem_off = 18 * KD * sizeof(float);        // 82944
    cudaFuncSetAttribute(off_conv_kernel,
                         cudaFuncAttributeMaxDynamicSharedMemorySize, smem_off);
    const int smem_gemm = STAGES * 16384;                // 81920
    cudaFuncSetAttribute(gemm_kernel,
                         cudaFuncAttributeMaxDynamicSharedMemorySize, smem_gemm);

    wprep_kernel<<<(COUT * KD + 255) / 256, 256>>>(w_def);
    off_conv_kernel<<<(NPIX / 4) / 128, 128, smem_off>>>(x, w_off, b_off);
    sample_kernel<<<dim3(HW / 256, 9, B_), 256>>>(x);
    gemm_kernel<<<dim3(2, NPIX / 128), 256, smem_gemm>>>(out);
}